// round 3
// baseline (speedup 1.0000x reference)
#include <cuda_runtime.h>
#include <stdint.h>
#include <math.h>

// Inputs: 0 v_data f32[524288*16], 1 cond f32[524288], 2 W f32[16*32], 3 b f32[16],
// 4 c f32[32], 5 W1 f32[64], 6 b1 f32[64], 7 W2 f32[64*96], 8 b2 f32[96], 9 k int[1]
// output: f32[1]

#define NV 16
#define NH 32
#define TPB 128
#define MAXK 64
#define MAXBLK 8192

typedef unsigned long long u64;

__device__ float g_part[MAXBLK];
__device__ unsigned int g_ticket;   // zero-init; reset by last block each launch

// ---------------------------------------------------------------------------
// threefry2x32 (JAX partitionable semantics, verified bit-exact)
// ---------------------------------------------------------------------------
__device__ __forceinline__ uint32_t rotl32(uint32_t x, int r) {
    return __funnelshift_l(x, x, r);
}

__device__ __forceinline__ uint2 tf2x32(uint2 key, uint32_t chi, uint32_t clo) {
    uint32_t k0 = key.x, k1 = key.y, k2 = k0 ^ k1 ^ 0x1BD11BDAu;
    uint32_t x0 = chi + k0, x1 = clo + k1;
#define TFR(r) { x0 += x1; x1 = rotl32(x1, r); x1 ^= x0; }
    TFR(13) TFR(15) TFR(26) TFR(6)   x0 += k1; x1 += k2 + 1u;
    TFR(17) TFR(29) TFR(16) TFR(24)  x0 += k2; x1 += k0 + 2u;
    TFR(13) TFR(15) TFR(26) TFR(6)   x0 += k0; x1 += k1 + 3u;
    TFR(17) TFR(29) TFR(16) TFR(24)  x0 += k1; x1 += k2 + 4u;
    TFR(13) TFR(15) TFR(26) TFR(6)   x0 += k2; x1 += k0 + 5u;
#undef TFR
    return make_uint2(x0, x1);
}

struct TFK { uint32_t k0, k1, k2, c1, c2, c3, c4, c5; };

__device__ __forceinline__ TFK mk_tfk(uint2 key) {
    TFK K;
    K.k0 = key.x; K.k1 = key.y; K.k2 = K.k0 ^ K.k1 ^ 0x1BD11BDAu;
    K.c1 = K.k2 + 1u; K.c2 = K.k0 + 2u; K.c3 = K.k1 + 3u;
    K.c4 = K.k2 + 4u; K.c5 = K.k0 + 5u;
    return K;
}

__device__ __forceinline__ uint32_t tf_bits(const TFK K, uint32_t idx) {
    uint32_t x0 = K.k0, x1 = idx + K.k1;
#define TFR(r) { x0 += x1; x1 = rotl32(x1, r); x1 ^= x0; }
    TFR(13) TFR(15) TFR(26) TFR(6)   x0 += K.k1; x1 += K.c1;
    TFR(17) TFR(29) TFR(16) TFR(24)  x0 += K.k2; x1 += K.c2;
    TFR(13) TFR(15) TFR(26) TFR(6)   x0 += K.k0; x1 += K.c3;
    TFR(17) TFR(29) TFR(16) TFR(24)  x0 += K.k1; x1 += K.c4;
    TFR(13) TFR(15) TFR(26) TFR(6)   x0 += K.k2; x1 += K.c5;
#undef TFR
    return x0 ^ x1;
}

__device__ __forceinline__ float u01(uint32_t bits) {
    return __uint_as_float((bits >> 9) | 0x3f800000u) - 1.0f;
}
// softplus: fast exp, accurate log1p
__device__ __forceinline__ float softplusf(float x) {
    return fmaxf(x, 0.0f) + log1pf(__expf(-fabsf(x)));
}

// packed fp32x2 helpers (per-lane fma.rn -> bit-identical to scalar fmaf)
__device__ __forceinline__ void ffma2(u64& a, u64 b, u64 c) {
    asm("fma.rn.f32x2 %0, %1, %2, %0;" : "+l"(a) : "l"(b), "l"(c));
}
__device__ __forceinline__ u64 fadd2(u64 a, u64 b) {
    u64 r;
    asm("add.rn.f32x2 %0, %1, %2;" : "=l"(r) : "l"(a), "l"(b));
    return r;
}
__device__ __forceinline__ u64 dup2(float h) {
    u64 r;
    asm("mov.b64 %0, {%1, %1};" : "=l"(r) : "r"(__float_as_uint(h)));
    return r;
}
__device__ __forceinline__ u64 pack2(float a, float b) {
    u64 r;
    asm("mov.b64 %0, {%1, %2};" : "=l"(r) : "r"(__float_as_uint(a)), "r"(__float_as_uint(b)));
    return r;
}
__device__ __forceinline__ float lo32f(u64 v) { return __uint_as_float((uint32_t)v); }
__device__ __forceinline__ float hi32f(u64 v) { return __uint_as_float((uint32_t)(v >> 32)); }

union F4U { float4 f; u64 u[2]; };

// ---------------------------------------------------------------------------
// free energy: -(v.b_mod) - sum_j softplus(v.W_j + c_mod_j)
// paired dots; bit-identical accumulation order vs scalar j-ascending version
// ---------------------------------------------------------------------------
__device__ __forceinline__ float free_energy(const u64 vdup[NV],
                                             const u64 bmod[8],
                                             const u64* scmodp_col,   // stride TPB
                                             const u64* sWtP) {
    float e = 0.0f;
#pragma unroll
    for (int p = 0; p < 8; ++p) {
        e = fmaf(lo32f(vdup[2 * p]),     lo32f(bmod[p]), e);
        e = fmaf(lo32f(vdup[2 * p + 1]), hi32f(bmod[p]), e);
    }
    float esp = 0.0f;
#pragma unroll 2
    for (int jp = 0; jp < 16; ++jp) {
        u64 sp = scmodp_col[jp * TPB];
        const u64* wp = &sWtP[jp * NV];
#pragma unroll
        for (int i = 0; i < NV; ++i) ffma2(sp, vdup[i], wp[i]);
        esp += softplusf(lo32f(sp));
        esp += softplusf(hi32f(sp));
    }
    return -e - esp;
}

// ---------------------------------------------------------------------------
// single fused kernel
// ---------------------------------------------------------------------------
__global__ void __launch_bounds__(TPB, 5)
rbm_fused(const float* __restrict__ v_data,
          const float* __restrict__ cond,
          const float* __restrict__ W,
          const float* __restrict__ bias_b,
          const float* __restrict__ bias_c,
          const float* __restrict__ W1,
          const float* __restrict__ b1,
          const float* __restrict__ W2,
          const float* __restrict__ b2,
          const int* __restrict__ kp,
          float* __restrict__ out,
          int batch) {
    __shared__ __align__(16) float sWt[NH * NV];   // W^T rows: sWt[j*16+i]
    __shared__ __align__(16) u64   sWtP[16 * NV];  // paired: (W[i][2jp], W[i][2jp+1])
    __shared__ __align__(16) float sM[64 * 48];    // folded MLP matrix
    __shared__ float sBase[48];
    __shared__ float sW1[64], sb1[64];
    __shared__ uint2 sck[MAXK];
    __shared__ uint2 sk1[MAXK], sk2[MAXK];
    __shared__ int   skk;
    __shared__ u64   scmodp[16 * TPB];             // paired c_mod per thread, 16KB
    __shared__ float swarp[TPB / 32];
    __shared__ int   sIsLast;
    __shared__ double sd[TPB];

    const int t = threadIdx.x;

    // ---- per-block init (redundant across blocks; cheap) ----
    for (int idx = t; idx < NH * NV; idx += TPB) {
        int j = idx / NV, i = idx % NV;
        sWt[idx] = W[i * NH + j];
    }
    for (int idx = t; idx < 16 * NV; idx += TPB) {
        int jp = idx / NV, i = idx % NV;
        sWtP[idx] = pack2(W[i * NH + 2 * jp], W[i * NH + 2 * jp + 1]);
    }
    for (int idx = t; idx < 64 * 48; idx += TPB) {
        int j = idx / 48, q = idx % 48;
        float m;
        if (q < NV) {
            m = bias_b[q] * W2[j * 96 + q] + W2[j * 96 + 16 + q];
        } else {
            int l = q - NV;
            m = bias_c[l] * W2[j * 96 + 32 + l] + W2[j * 96 + 64 + l];
        }
        sM[idx] = m;
    }
    if (t < 48) {
        float bs;
        if (t < NV) bs = bias_b[t] * (1.0f + b2[t]) + b2[16 + t];
        else {
            int l = t - NV;
            bs = bias_c[l] * (1.0f + b2[32 + l]) + b2[64 + l];
        }
        sBase[t] = bs;
    }
    if (t < 64) { sW1[t] = W1[t]; sb1[t] = b1[t]; }
    if (t == 0) {
        int kkv = *kp;
        if (kkv < 0) kkv = 0;
        if (kkv > MAXK) kkv = MAXK;
        skk = kkv;
        uint2 key = make_uint2(0u, 42u);
        for (int s = 0; s < kkv; ++s) {
            sck[s] = key;
            key = tf2x32(key, 0u, 0u);
        }
    }
    __syncthreads();
    const int kk = skk;
    if (t < kk)                      sk1[t]      = tf2x32(sck[t],      0u, 1u);
    else if (t >= 64 && t < 64 + kk) sk2[t - 64] = tf2x32(sck[t - 64], 0u, 2u);
    __syncthreads();

    // ---- per-sample work ----
    const int sample = blockIdx.x * TPB + t;
    float loss = 0.0f;

    if (sample < batch) {
        // conditioning MLP (folded), packed fp32x2 accumulate
        float cb = cond[sample];
        u64 modp[24];
#pragma unroll
        for (int q = 0; q < 24; ++q) modp[q] = pack2(sBase[2 * q], sBase[2 * q + 1]);
        const u64* sM2 = reinterpret_cast<const u64*>(sM);
#pragma unroll 4
        for (int j = 0; j < 64; ++j) {
            float tj = tanhf(fmaf(cb, sW1[j], sb1[j]));
            u64 tj2 = dup2(tj);
#pragma unroll
            for (int q = 0; q < 24; ++q) ffma2(modp[q], tj2, sM2[j * 24 + q]);
        }

        // b_mod (reg pairs over i); c_mod (smem pairs over j, per-thread column)
        u64 bmod[8];
#pragma unroll
        for (int p = 0; p < 8; ++p) bmod[p] = modp[p];
        u64* scmodp_col = &scmodp[t];
#pragma unroll
        for (int jp = 0; jp < 16; ++jp) scmodp_col[jp * TPB] = modp[8 + jp];

        // load v_data as duplicated pairs
        u64 vdup[NV];
        {
            const float4* vd = reinterpret_cast<const float4*>(v_data + (size_t)sample * NV);
#pragma unroll
            for (int r = 0; r < 4; ++r) {
                float4 x = vd[r];
                vdup[r * 4 + 0] = dup2(x.x); vdup[r * 4 + 1] = dup2(x.y);
                vdup[r * 4 + 2] = dup2(x.z); vdup[r * 4 + 3] = dup2(x.w);
            }
        }

        float fe_data = free_energy(vdup, bmod, scmodp_col, sWtP);

        // ---- Gibbs chain ----
        const uint32_t base_h = (uint32_t)sample * NH;
        const uint32_t base_v = (uint32_t)sample * NV;

        for (int s = 0; s < kk; ++s) {
            const TFK K1 = mk_tfk(sk1[s]);
            u64 acc[8];
#pragma unroll
            for (int p = 0; p < 8; ++p) acc[p] = 0ull;

#pragma unroll 2
            for (int jp = 0; jp < 16; ++jp) {
                // paired dot: s_{2jp}, s_{2jp+1}
                u64 sp = scmodp_col[jp * TPB];
                const u64* wpp = &sWtP[jp * NV];
#pragma unroll
                for (int i = 0; i < NV; ++i) ffma2(sp, vdup[i], wpp[i]);

                // two bernoulli draws: u*(1+e^-s) < 1  <=>  u < sigmoid(s)
                float e0 = __expf(-lo32f(sp));
                float u0 = u01(tf_bits(K1, base_h + (uint32_t)(2 * jp)));
                float h0 = (fmaf(u0, e0, u0) < 1.0f) ? 1.0f : 0.0f;
                float e1 = __expf(-hi32f(sp));
                float u1 = u01(tf_bits(K1, base_h + (uint32_t)(2 * jp + 1)));
                float h1 = (fmaf(u1, e1, u1) < 1.0f) ? 1.0f : 0.0f;

                // acc += h0 * W_{2jp} + h1 * W_{2jp+1}  (packed over i)
                u64 h20 = dup2(h0), h21 = dup2(h1);
                const F4U* wa = reinterpret_cast<const F4U*>(&sWt[(2 * jp) * NV]);
                const F4U* wb = reinterpret_cast<const F4U*>(&sWt[(2 * jp + 1) * NV]);
                F4U a0 = wa[0], a1 = wa[1], a2 = wa[2], a3 = wa[3];
                ffma2(acc[0], h20, a0.u[0]); ffma2(acc[1], h20, a0.u[1]);
                ffma2(acc[2], h20, a1.u[0]); ffma2(acc[3], h20, a1.u[1]);
                ffma2(acc[4], h20, a2.u[0]); ffma2(acc[5], h20, a2.u[1]);
                ffma2(acc[6], h20, a3.u[0]); ffma2(acc[7], h20, a3.u[1]);
                F4U b0v = wb[0], b1v = wb[1], b2v = wb[2], b3v = wb[3];
                ffma2(acc[0], h21, b0v.u[0]); ffma2(acc[1], h21, b0v.u[1]);
                ffma2(acc[2], h21, b1v.u[0]); ffma2(acc[3], h21, b1v.u[1]);
                ffma2(acc[4], h21, b2v.u[0]); ffma2(acc[5], h21, b2v.u[1]);
                ffma2(acc[6], h21, b3v.u[0]); ffma2(acc[7], h21, b3v.u[1]);
            }

            const TFK K2 = mk_tfk(sk2[s]);
#pragma unroll
            for (int p = 0; p < 8; ++p) {
                u64 sv2 = fadd2(acc[p], bmod[p]);   // per-lane add.rn == scalar a+b
                float e0 = __expf(-lo32f(sv2));
                float u0 = u01(tf_bits(K2, base_v + (uint32_t)(2 * p)));
                float v0 = (fmaf(u0, e0, u0) < 1.0f) ? 1.0f : 0.0f;
                float e1 = __expf(-hi32f(sv2));
                float u1 = u01(tf_bits(K2, base_v + (uint32_t)(2 * p + 1)));
                float v1 = (fmaf(u1, e1, u1) < 1.0f) ? 1.0f : 0.0f;
                vdup[2 * p]     = dup2(v0);
                vdup[2 * p + 1] = dup2(v1);
            }
        }

        float fe_model = free_energy(vdup, bmod, scmodp_col, sWtP);
        loss = fe_data - fe_model;
    }

    // ---- deterministic block reduction ----
#pragma unroll
    for (int off = 16; off > 0; off >>= 1)
        loss += __shfl_down_sync(0xffffffffu, loss, off);
    if ((t & 31) == 0) swarp[t >> 5] = loss;
    __syncthreads();
    if (t == 0) {
        float tot = 0.0f;
#pragma unroll
        for (int wgi = 0; wgi < TPB / 32; ++wgi) tot += swarp[wgi];
        g_part[blockIdx.x] = tot;
        __threadfence();
        unsigned r = atomicAdd(&g_ticket, 1u);
        sIsLast = (r == gridDim.x - 1) ? 1 : 0;
    }
    __syncthreads();

    // ---- last block: final deterministic reduction ----
    if (sIsLast) {
        __threadfence();
        double accd = 0.0;
        for (int idx = t; idx < (int)gridDim.x; idx += TPB)
            accd += (double)g_part[idx];
        sd[t] = accd;
        __syncthreads();
#pragma unroll
        for (int off = TPB / 2; off > 0; off >>= 1) {
            if (t < off) sd[t] += sd[t + off];
            __syncthreads();
        }
        if (t == 0) {
            out[0] = (float)(sd[0] / (double)batch);
            g_ticket = 0u;   // reset for next graph replay
        }
    }
}

// ---------------------------------------------------------------------------
extern "C" void kernel_launch(void* const* d_in, const int* in_sizes, int n_in,
                              void* d_out, int out_size) {
    const float* v_data = (const float*)d_in[0];
    const float* cond   = (const float*)d_in[1];
    const float* W      = (const float*)d_in[2];
    const float* bias_b = (const float*)d_in[3];
    const float* bias_c = (const float*)d_in[4];
    const float* W1     = (const float*)d_in[5];
    const float* b1     = (const float*)d_in[6];
    const float* W2     = (const float*)d_in[7];
    const float* b2     = (const float*)d_in[8];
    const int*   kp     = (const int*)d_in[9];

    int batch = in_sizes[0] / NV;   // 524288
    int grid = (batch + TPB - 1) / TPB;
    if (grid > MAXBLK) grid = MAXBLK;

    rbm_fused<<<grid, TPB>>>(v_data, cond, W, bias_b, bias_c, W1, b1, W2, b2,
                             kp, (float*)d_out, batch);
}

// round 4
// speedup vs baseline: 1.1137x; 1.1137x over previous
#include <cuda_runtime.h>
#include <stdint.h>
#include <math.h>

// Inputs: 0 v_data f32[524288*16], 1 cond f32[524288], 2 W f32[16*32], 3 b f32[16],
// 4 c f32[32], 5 W1 f32[64], 6 b1 f32[64], 7 W2 f32[64*96], 8 b2 f32[96], 9 k int[1]
// output: f32[1]

#define NV 16
#define NH 32
#define TPB 128
#define MAXK 64
#define MAXBLK 8192

typedef unsigned long long u64;

__device__ float g_part[MAXBLK];
__device__ unsigned int g_ticket;   // zero-init; reset by last block each launch

// ---------------------------------------------------------------------------
// threefry2x32 (JAX partitionable semantics, verified bit-exact)
// ---------------------------------------------------------------------------
__device__ __forceinline__ uint32_t rotl32(uint32_t x, int r) {
    return __funnelshift_l(x, x, r);
}

__device__ __forceinline__ uint2 tf2x32(uint2 key, uint32_t chi, uint32_t clo) {
    uint32_t k0 = key.x, k1 = key.y, k2 = k0 ^ k1 ^ 0x1BD11BDAu;
    uint32_t x0 = chi + k0, x1 = clo + k1;
#define TFR(r) { x0 += x1; x1 = rotl32(x1, r); x1 ^= x0; }
    TFR(13) TFR(15) TFR(26) TFR(6)   x0 += k1; x1 += k2 + 1u;
    TFR(17) TFR(29) TFR(16) TFR(24)  x0 += k2; x1 += k0 + 2u;
    TFR(13) TFR(15) TFR(26) TFR(6)   x0 += k0; x1 += k1 + 3u;
    TFR(17) TFR(29) TFR(16) TFR(24)  x0 += k1; x1 += k2 + 4u;
    TFR(13) TFR(15) TFR(26) TFR(6)   x0 += k2; x1 += k0 + 5u;
#undef TFR
    return make_uint2(x0, x1);
}

struct TFK { uint32_t k0, k1, k2, c1, c2, c3, c4, c5; };

__device__ __forceinline__ TFK mk_tfk(uint2 key) {
    TFK K;
    K.k0 = key.x; K.k1 = key.y; K.k2 = K.k0 ^ K.k1 ^ 0x1BD11BDAu;
    K.c1 = K.k2 + 1u; K.c2 = K.k0 + 2u; K.c3 = K.k1 + 3u;
    K.c4 = K.k2 + 4u; K.c5 = K.k0 + 5u;
    return K;
}

// x1init = idx + K.k1 precombined by caller (integer add is associative/exact)
__device__ __forceinline__ uint32_t tf_bits_pc(const TFK K, uint32_t x1init) {
    uint32_t x0 = K.k0, x1 = x1init;
#define TFR(r) { x0 += x1; x1 = rotl32(x1, r); x1 ^= x0; }
    TFR(13) TFR(15) TFR(26) TFR(6)   x0 += K.k1; x1 += K.c1;
    TFR(17) TFR(29) TFR(16) TFR(24)  x0 += K.k2; x1 += K.c2;
    TFR(13) TFR(15) TFR(26) TFR(6)   x0 += K.k0; x1 += K.c3;
    TFR(17) TFR(29) TFR(16) TFR(24)  x0 += K.k1; x1 += K.c4;
    TFR(13) TFR(15) TFR(26) TFR(6)   x0 += K.k2; x1 += K.c5;
#undef TFR
    return x0 ^ x1;
}

// (bits>>9)+0x3f800000 == (bits>>9)|0x3f800000 (disjoint bits); ADD form lets
// ptxas alternate IMAD onto the fma pipe.
__device__ __forceinline__ float u01(uint32_t bits) {
    return __uint_as_float((bits >> 9) + 0x3f800000u) - 1.0f;
}
__device__ __forceinline__ float softplusf(float x) {
    return fmaxf(x, 0.0f) + log1pf(__expf(-fabsf(x)));
}

// packed fp32x2 helpers (per-lane fma.rn)
__device__ __forceinline__ void ffma2(u64& a, u64 b, u64 c) {
    asm("fma.rn.f32x2 %0, %1, %2, %0;" : "+l"(a) : "l"(b), "l"(c));
}
__device__ __forceinline__ u64 fadd2(u64 a, u64 b) {
    u64 r;
    asm("add.rn.f32x2 %0, %1, %2;" : "=l"(r) : "l"(a), "l"(b));
    return r;
}
__device__ __forceinline__ u64 dup2(float h) {
    u64 r;
    asm("mov.b64 %0, {%1, %1};" : "=l"(r) : "r"(__float_as_uint(h)));
    return r;
}
__device__ __forceinline__ u64 pack2(float a, float b) {
    u64 r;
    asm("mov.b64 %0, {%1, %2};" : "=l"(r) : "r"(__float_as_uint(a)), "r"(__float_as_uint(b)));
    return r;
}
__device__ __forceinline__ float lo32f(u64 v) { return __uint_as_float((uint32_t)v); }
__device__ __forceinline__ float hi32f(u64 v) { return __uint_as_float((uint32_t)(v >> 32)); }

// ---------------------------------------------------------------------------
// free energy: -(v.b_mod) - sum_j softplus(v.W_j + c_mod_j)
// v packed over i-pairs; even/odd split then horizontal add.
// ---------------------------------------------------------------------------
__device__ __forceinline__ float free_energy(const u64 vpack[8],
                                             const u64* sbmod_col,    // stride TPB
                                             const u64* scmodp_col,   // stride TPB
                                             const u64* sWtI) {
    u64 e2 = 0ull;
#pragma unroll
    for (int p = 0; p < 8; ++p) ffma2(e2, vpack[p], sbmod_col[p * TPB]);
    float e = lo32f(e2) + hi32f(e2);

    float esp = 0.0f;
#pragma unroll 2
    for (int jp = 0; jp < 16; ++jp) {
        u64 cpair = scmodp_col[jp * TPB];
#pragma unroll
        for (int sub = 0; sub < 2; ++sub) {
            int j = 2 * jp + sub;
            float cj = sub ? hi32f(cpair) : lo32f(cpair);
            u64 sp = pack2(cj, 0.0f);
            const u64* wI = &sWtI[j * 8];
#pragma unroll
            for (int p = 0; p < 8; ++p) ffma2(sp, vpack[p], wI[p]);
            esp += softplusf(lo32f(sp) + hi32f(sp));
        }
    }
    return -e - esp;
}

// ---------------------------------------------------------------------------
// single fused kernel
// ---------------------------------------------------------------------------
__global__ void __launch_bounds__(TPB, 5)
rbm_fused(const float* __restrict__ v_data,
          const float* __restrict__ cond,
          const float* __restrict__ W,
          const float* __restrict__ bias_b,
          const float* __restrict__ bias_c,
          const float* __restrict__ W1,
          const float* __restrict__ b1,
          const float* __restrict__ W2,
          const float* __restrict__ b2,
          const int* __restrict__ kp,
          float* __restrict__ out,
          int batch) {
    __shared__ __align__(16) u64   sWtI[NH * 8];   // (W[2p][j], W[2p+1][j]) per j
    __shared__ __align__(16) float sM[64 * 48];    // folded MLP matrix
    __shared__ float sBase[48];
    __shared__ float sW1[64], sb1[64];
    __shared__ uint2 sck[MAXK];
    __shared__ uint2 sk1[MAXK], sk2[MAXK];
    __shared__ int   skk;
    __shared__ u64   scmodp[16 * TPB];             // c_mod pairs (over j), 16KB
    __shared__ u64   sbmod[8 * TPB];               // b_mod pairs (over i), 8KB
    __shared__ float swarp[TPB / 32];
    __shared__ int   sIsLast;
    __shared__ double sd[TPB];

    const int t = threadIdx.x;

    // ---- per-block init (redundant across blocks; cheap) ----
    for (int idx = t; idx < NH * 8; idx += TPB) {
        int j = idx / 8, p = idx % 8;
        sWtI[idx] = pack2(W[(2 * p) * NH + j], W[(2 * p + 1) * NH + j]);
    }
    for (int idx = t; idx < 64 * 48; idx += TPB) {
        int j = idx / 48, q = idx % 48;
        float m;
        if (q < NV) {
            m = bias_b[q] * W2[j * 96 + q] + W2[j * 96 + 16 + q];
        } else {
            int l = q - NV;
            m = bias_c[l] * W2[j * 96 + 32 + l] + W2[j * 96 + 64 + l];
        }
        sM[idx] = m;
    }
    if (t < 48) {
        float bs;
        if (t < NV) bs = bias_b[t] * (1.0f + b2[t]) + b2[16 + t];
        else {
            int l = t - NV;
            bs = bias_c[l] * (1.0f + b2[32 + l]) + b2[64 + l];
        }
        sBase[t] = bs;
    }
    if (t < 64) { sW1[t] = W1[t]; sb1[t] = b1[t]; }
    if (t == 0) {
        int kkv = *kp;
        if (kkv < 0) kkv = 0;
        if (kkv > MAXK) kkv = MAXK;
        skk = kkv;
        uint2 key = make_uint2(0u, 42u);
        for (int s = 0; s < kkv; ++s) {
            sck[s] = key;
            key = tf2x32(key, 0u, 0u);
        }
    }
    __syncthreads();
    const int kk = skk;
    if (t < kk)                      sk1[t]      = tf2x32(sck[t],      0u, 1u);
    else if (t >= 64 && t < 64 + kk) sk2[t - 64] = tf2x32(sck[t - 64], 0u, 2u);
    __syncthreads();

    // ---- per-sample work ----
    const int sample = blockIdx.x * TPB + t;
    float loss = 0.0f;

    if (sample < batch) {
        // conditioning MLP (folded), packed fp32x2 accumulate
        float cb = cond[sample];
        u64 modp[24];
#pragma unroll
        for (int q = 0; q < 24; ++q) modp[q] = pack2(sBase[2 * q], sBase[2 * q + 1]);
        const u64* sM2 = reinterpret_cast<const u64*>(sM);
#pragma unroll 4
        for (int j = 0; j < 64; ++j) {
            float tj = tanhf(fmaf(cb, sW1[j], sb1[j]));
            u64 tj2 = dup2(tj);
#pragma unroll
            for (int q = 0; q < 24; ++q) ffma2(modp[q], tj2, sM2[j * 24 + q]);
        }

        // b_mod and c_mod into per-thread smem columns
        u64* sbmod_col = &sbmod[t];
        u64* scmodp_col = &scmodp[t];
#pragma unroll
        for (int p = 0; p < 8; ++p) sbmod_col[p * TPB] = modp[p];
#pragma unroll
        for (int jp = 0; jp < 16; ++jp) scmodp_col[jp * TPB] = modp[8 + jp];

        // load v_data as natural i-pairs (consecutive floats -> (lo,hi))
        u64 vpack[8];
        {
            const u64* vd = reinterpret_cast<const u64*>(v_data + (size_t)sample * NV);
#pragma unroll
            for (int p = 0; p < 8; ++p) vpack[p] = vd[p];
        }

        float fe_data = free_energy(vpack, sbmod_col, scmodp_col, sWtI);

        // ---- Gibbs chain ----
        const uint32_t base_h = (uint32_t)sample * NH;
        const uint32_t base_v = (uint32_t)sample * NV;

        for (int s = 0; s < kk; ++s) {
            const TFK K1 = mk_tfk(sk1[s]);
            const uint32_t hoff = base_h + K1.k1;   // x1init for j=0
            u64 acc[8];
#pragma unroll
            for (int p = 0; p < 8; ++p) acc[p] = 0ull;

#pragma unroll 2
            for (int jp = 0; jp < 16; ++jp) {
                u64 cpair = scmodp_col[jp * TPB];
#pragma unroll
                for (int sub = 0; sub < 2; ++sub) {
                    const int j = 2 * jp + sub;
                    float cj = sub ? hi32f(cpair) : lo32f(cpair);
                    u64 sp = pack2(cj, 0.0f);
                    const u64* wI = &sWtI[j * 8];
                    u64 w0 = wI[0], w1 = wI[1], w2 = wI[2], w3 = wI[3];
                    u64 w4 = wI[4], w5 = wI[5], w6 = wI[6], w7 = wI[7];
                    ffma2(sp, vpack[0], w0); ffma2(sp, vpack[1], w1);
                    ffma2(sp, vpack[2], w2); ffma2(sp, vpack[3], w3);
                    ffma2(sp, vpack[4], w4); ffma2(sp, vpack[5], w5);
                    ffma2(sp, vpack[6], w6); ffma2(sp, vpack[7], w7);
                    float sj = lo32f(sp) + hi32f(sp);
                    float ex = __expf(-sj);
                    float u = u01(tf_bits_pc(K1, hoff + (uint32_t)j));
                    float h = (fmaf(u, ex, u) < 1.0f) ? 1.0f : 0.0f;
                    u64 h2 = dup2(h);
                    ffma2(acc[0], h2, w0); ffma2(acc[1], h2, w1);
                    ffma2(acc[2], h2, w2); ffma2(acc[3], h2, w3);
                    ffma2(acc[4], h2, w4); ffma2(acc[5], h2, w5);
                    ffma2(acc[6], h2, w6); ffma2(acc[7], h2, w7);
                }
            }

            const TFK K2 = mk_tfk(sk2[s]);
            const uint32_t voff = base_v + K2.k1;
#pragma unroll
            for (int p = 0; p < 8; ++p) {
                u64 sv2 = fadd2(acc[p], sbmod_col[p * TPB]);
                float e0 = __expf(-lo32f(sv2));
                float u0 = u01(tf_bits_pc(K2, voff + (uint32_t)(2 * p)));
                float v0 = (fmaf(u0, e0, u0) < 1.0f) ? 1.0f : 0.0f;
                float e1 = __expf(-hi32f(sv2));
                float u1 = u01(tf_bits_pc(K2, voff + (uint32_t)(2 * p + 1)));
                float v1 = (fmaf(u1, e1, u1) < 1.0f) ? 1.0f : 0.0f;
                vpack[p] = pack2(v0, v1);
            }
        }

        float fe_model = free_energy(vpack, sbmod_col, scmodp_col, sWtI);
        loss = fe_data - fe_model;
    }

    // ---- deterministic block reduction ----
#pragma unroll
    for (int off = 16; off > 0; off >>= 1)
        loss += __shfl_down_sync(0xffffffffu, loss, off);
    if ((t & 31) == 0) swarp[t >> 5] = loss;
    __syncthreads();
    if (t == 0) {
        float tot = 0.0f;
#pragma unroll
        for (int wgi = 0; wgi < TPB / 32; ++wgi) tot += swarp[wgi];
        g_part[blockIdx.x] = tot;
        __threadfence();
        unsigned r = atomicAdd(&g_ticket, 1u);
        sIsLast = (r == gridDim.x - 1) ? 1 : 0;
    }
    __syncthreads();

    // ---- last block: final deterministic reduction ----
    if (sIsLast) {
        __threadfence();
        double accd = 0.0;
        for (int idx = t; idx < (int)gridDim.x; idx += TPB)
            accd += (double)g_part[idx];
        sd[t] = accd;
        __syncthreads();
#pragma unroll
        for (int off = TPB / 2; off > 0; off >>= 1) {
            if (t < off) sd[t] += sd[t + off];
            __syncthreads();
        }
        if (t == 0) {
            out[0] = (float)(sd[0] / (double)batch);
            g_ticket = 0u;   // reset for next graph replay
        }
    }
}

// ---------------------------------------------------------------------------
extern "C" void kernel_launch(void* const* d_in, const int* in_sizes, int n_in,
                              void* d_out, int out_size) {
    const float* v_data = (const float*)d_in[0];
    const float* cond   = (const float*)d_in[1];
    const float* W      = (const float*)d_in[2];
    const float* bias_b = (const float*)d_in[3];
    const float* bias_c = (const float*)d_in[4];
    const float* W1     = (const float*)d_in[5];
    const float* b1     = (const float*)d_in[6];
    const float* W2     = (const float*)d_in[7];
    const float* b2     = (const float*)d_in[8];
    const int*   kp     = (const int*)d_in[9];

    int batch = in_sizes[0] / NV;   // 524288
    int grid = (batch + TPB - 1) / TPB;
    if (grid > MAXBLK) grid = MAXBLK;

    rbm_fused<<<grid, TPB>>>(v_data, cond, W, bias_b, bias_c, W1, b1, W2, b2,
                             kp, (float*)d_out, batch);
}

// round 5
// speedup vs baseline: 1.1155x; 1.0017x over previous
#include <cuda_runtime.h>
#include <stdint.h>
#include <math.h>

// Inputs: 0 v_data f32[524288*16], 1 cond f32[524288], 2 W f32[16*32], 3 b f32[16],
// 4 c f32[32], 5 W1 f32[64], 6 b1 f32[64], 7 W2 f32[64*96], 8 b2 f32[96], 9 k int[1]
// output: f32[1]

#define NV 16
#define NH 32
#define TPB 128
#define MAXK 64
#define MAXBLK 8192

typedef unsigned long long u64;

#define NEG_LOG2E (-1.44269504088896340736f)
#define NLN2      (-0.69314718055994530942f)

__device__ float g_part[MAXBLK];
__device__ unsigned int g_ticket;   // zero-init; reset by last block each launch

// ---------------------------------------------------------------------------
// threefry2x32 (JAX partitionable semantics, verified bit-exact)
// ---------------------------------------------------------------------------
__device__ __forceinline__ uint32_t rotl32(uint32_t x, int r) {
    return __funnelshift_l(x, x, r);
}

__device__ __forceinline__ uint2 tf2x32(uint2 key, uint32_t chi, uint32_t clo) {
    uint32_t k0 = key.x, k1 = key.y, k2 = k0 ^ k1 ^ 0x1BD11BDAu;
    uint32_t x0 = chi + k0, x1 = clo + k1;
#define TFR(r) { x0 += x1; x1 = rotl32(x1, r); x1 ^= x0; }
    TFR(13) TFR(15) TFR(26) TFR(6)   x0 += k1; x1 += k2 + 1u;
    TFR(17) TFR(29) TFR(16) TFR(24)  x0 += k2; x1 += k0 + 2u;
    TFR(13) TFR(15) TFR(26) TFR(6)   x0 += k0; x1 += k1 + 3u;
    TFR(17) TFR(29) TFR(16) TFR(24)  x0 += k1; x1 += k2 + 4u;
    TFR(13) TFR(15) TFR(26) TFR(6)   x0 += k2; x1 += k0 + 5u;
#undef TFR
    return make_uint2(x0, x1);
}

struct TFK { uint32_t k0, k1, k2, c1, c2, c3, c4, c5; };

__device__ __forceinline__ TFK mk_tfk(uint2 key) {
    TFK K;
    K.k0 = key.x; K.k1 = key.y; K.k2 = K.k0 ^ K.k1 ^ 0x1BD11BDAu;
    K.c1 = K.k2 + 1u; K.c2 = K.k0 + 2u; K.c3 = K.k1 + 3u;
    K.c4 = K.k2 + 4u; K.c5 = K.k0 + 5u;
    return K;
}

// x1init = idx + K.k1 precombined by caller (integer add exact)
__device__ __forceinline__ uint32_t tf_bits_pc(const TFK K, uint32_t x1init) {
    uint32_t x0 = K.k0, x1 = x1init;
#define TFR(r) { x0 += x1; x1 = rotl32(x1, r); x1 ^= x0; }
    TFR(13) TFR(15) TFR(26) TFR(6)   x0 += K.k1; x1 += K.c1;
    TFR(17) TFR(29) TFR(16) TFR(24)  x0 += K.k2; x1 += K.c2;
    TFR(13) TFR(15) TFR(26) TFR(6)   x0 += K.k0; x1 += K.c3;
    TFR(17) TFR(29) TFR(16) TFR(24)  x0 += K.k1; x1 += K.c4;
    TFR(13) TFR(15) TFR(26) TFR(6)   x0 += K.k2; x1 += K.c5;
#undef TFR
    return x0 ^ x1;
}

__device__ __forceinline__ float u01(uint32_t bits) {
    return __uint_as_float((bits >> 9) + 0x3f800000u) - 1.0f;
}
__device__ __forceinline__ float softplusf(float x) {
    return fmaxf(x, 0.0f) + log1pf(__expf(-fabsf(x)));
}
// raw ex2.approx: input is pre-scaled by -log2e, result = e^{-s}
__device__ __forceinline__ float ex2f(float x) {
    float r;
    asm("ex2.approx.f32 %0, %1;" : "=f"(r) : "f"(x));
    return r;
}

// packed fp32x2 helpers (per-lane .rn rounding)
__device__ __forceinline__ void ffma2(u64& a, u64 b, u64 c) {
    asm("fma.rn.f32x2 %0, %1, %2, %0;" : "+l"(a) : "l"(b), "l"(c));
}
__device__ __forceinline__ u64 fadd2(u64 a, u64 b) {
    u64 r;
    asm("add.rn.f32x2 %0, %1, %2;" : "=l"(r) : "l"(a), "l"(b));
    return r;
}
__device__ __forceinline__ u64 fmul2(u64 a, u64 b) {
    u64 r;
    asm("mul.rn.f32x2 %0, %1, %2;" : "=l"(r) : "l"(a), "l"(b));
    return r;
}
__device__ __forceinline__ u64 dup2(float h) {
    u64 r;
    asm("mov.b64 %0, {%1, %1};" : "=l"(r) : "r"(__float_as_uint(h)));
    return r;
}
__device__ __forceinline__ u64 pack2(float a, float b) {
    u64 r;
    asm("mov.b64 %0, {%1, %2};" : "=l"(r) : "r"(__float_as_uint(a)), "r"(__float_as_uint(b)));
    return r;
}
__device__ __forceinline__ float lo32f(u64 v) { return __uint_as_float((uint32_t)v); }
__device__ __forceinline__ float hi32f(u64 v) { return __uint_as_float((uint32_t)(v >> 32)); }

union U128 { uint4 q; u64 u[2]; };

// ---------------------------------------------------------------------------
// free energy from SCALED (×-log2e) weights/mods; unscale with ×(-ln2)
// ---------------------------------------------------------------------------
__device__ __forceinline__ float free_energy(const u64 vpack[8],
                                             const u64* sbmod_col,    // stride TPB
                                             const u64* scmodp_col,   // stride TPB
                                             const u64* sWtI) {
    u64 e2 = 0ull;
#pragma unroll
    for (int p = 0; p < 8; ++p) ffma2(e2, vpack[p], sbmod_col[p * TPB]);
    float e = (lo32f(e2) + hi32f(e2)) * NLN2;

    float esp = 0.0f;
#pragma unroll 2
    for (int jp = 0; jp < 16; ++jp) {
        u64 cpair = scmodp_col[jp * TPB];
#pragma unroll
        for (int sub = 0; sub < 2; ++sub) {
            int j = 2 * jp + sub;
            float cj = sub ? hi32f(cpair) : lo32f(cpair);
            u64 sp = pack2(cj, 0.0f);
            const u64* wI = &sWtI[j * 8];
#pragma unroll
            for (int p = 0; p < 8; ++p) ffma2(sp, vpack[p], wI[p]);
            esp += softplusf((lo32f(sp) + hi32f(sp)) * NLN2);
        }
    }
    return -e - esp;
}

// ---------------------------------------------------------------------------
// single fused kernel
// ---------------------------------------------------------------------------
__global__ void __launch_bounds__(TPB, 6)
rbm_fused(const float* __restrict__ v_data,
          const float* __restrict__ cond,
          const float* __restrict__ W,
          const float* __restrict__ bias_b,
          const float* __restrict__ bias_c,
          const float* __restrict__ W1,
          const float* __restrict__ b1,
          const float* __restrict__ W2,
          const float* __restrict__ b2,
          const int* __restrict__ kp,
          float* __restrict__ out,
          int batch) {
    // union region: phase A = folded MLP matrix sM (64*48 f32 = 12KB);
    // phase B = per-thread mod columns (8+16 u64 per thread = 24KB)
    __shared__ __align__(16) u64 sDyn[24 * TPB];   // 24KB
    __shared__ __align__(16) u64 sWtI[NH * 8];     // scaled weight pairs, 2KB
    __shared__ float sBase[48];
    __shared__ float sW1[64], sb1[64];
    __shared__ uint2 sck[MAXK];
    __shared__ uint2 sk1[MAXK], sk2[MAXK];
    __shared__ int   skk;
    __shared__ float swarp[TPB / 32];
    __shared__ int   sIsLast;
    __shared__ double sd[TPB];

    const int t = threadIdx.x;
    float* sMf = reinterpret_cast<float*>(sDyn);   // phase A view

    // ---- per-block init (redundant across blocks; cheap) ----
    for (int idx = t; idx < NH * 8; idx += TPB) {
        int j = idx / 8, p = idx % 8;
        sWtI[idx] = pack2(W[(2 * p) * NH + j] * NEG_LOG2E,
                          W[(2 * p + 1) * NH + j] * NEG_LOG2E);
    }
    for (int idx = t; idx < 64 * 48; idx += TPB) {
        int j = idx / 48, q = idx % 48;
        float m;
        if (q < NV) {
            m = bias_b[q] * W2[j * 96 + q] + W2[j * 96 + 16 + q];
        } else {
            int l = q - NV;
            m = bias_c[l] * W2[j * 96 + 32 + l] + W2[j * 96 + 64 + l];
        }
        sMf[idx] = m;
    }
    if (t < 48) {
        float bs;
        if (t < NV) bs = bias_b[t] * (1.0f + b2[t]) + b2[16 + t];
        else {
            int l = t - NV;
            bs = bias_c[l] * (1.0f + b2[32 + l]) + b2[64 + l];
        }
        sBase[t] = bs;
    }
    if (t < 64) { sW1[t] = W1[t]; sb1[t] = b1[t]; }
    if (t == 0) {
        int kkv = *kp;
        if (kkv < 0) kkv = 0;
        if (kkv > MAXK) kkv = MAXK;
        skk = kkv;
        uint2 key = make_uint2(0u, 42u);
        for (int s = 0; s < kkv; ++s) {
            sck[s] = key;
            key = tf2x32(key, 0u, 0u);
        }
    }
    __syncthreads();
    const int kk = skk;
    if (t < kk)                      sk1[t]      = tf2x32(sck[t],      0u, 1u);
    else if (t >= 64 && t < 64 + kk) sk2[t - 64] = tf2x32(sck[t - 64], 0u, 2u);
    __syncthreads();

    // ---- per-sample work ----
    const int sample = blockIdx.x * TPB + t;
    float loss = 0.0f;

    // phase A: conditioning MLP into registers (reads sM region)
    u64 modp[24];
    if (sample < batch) {
        float cb = cond[sample];
#pragma unroll
        for (int q = 0; q < 24; ++q) modp[q] = pack2(sBase[2 * q], sBase[2 * q + 1]);
        const u64* sM2 = sDyn;
#pragma unroll 4
        for (int j = 0; j < 64; ++j) {
            float tj = tanhf(fmaf(cb, sW1[j], sb1[j]));
            u64 tj2 = dup2(tj);
#pragma unroll
            for (int q = 0; q < 24; ++q) ffma2(modp[q], tj2, sM2[j * 24 + q]);
        }
    }
    __syncthreads();   // everyone done reading sM -> safe to overwrite

    // phase B: store SCALED mods into per-thread columns
    u64* sbmod_col  = &sDyn[t];             // 8 entries, stride TPB
    u64* scmodp_col = &sDyn[8 * TPB + t];   // 16 entries, stride TPB
    if (sample < batch) {
        const u64 sc2 = dup2(NEG_LOG2E);
#pragma unroll
        for (int p = 0; p < 8; ++p) sbmod_col[p * TPB] = fmul2(modp[p], sc2);
#pragma unroll
        for (int jp = 0; jp < 16; ++jp) scmodp_col[jp * TPB] = fmul2(modp[8 + jp], sc2);
    }

    if (sample < batch) {
        // load v_data as natural i-pairs
        u64 vpack[8];
        {
            const u64* vd = reinterpret_cast<const u64*>(v_data + (size_t)sample * NV);
#pragma unroll
            for (int p = 0; p < 8; ++p) vpack[p] = vd[p];
        }

        float fe_data = free_energy(vpack, sbmod_col, scmodp_col, sWtI);

        // ---- Gibbs chain ----
        const uint32_t base_h = (uint32_t)sample * NH;
        const uint32_t base_v = (uint32_t)sample * NV;

        for (int s = 0; s < kk; ++s) {
            const TFK K1 = mk_tfk(sk1[s]);
            const uint32_t hoff = base_h + K1.k1;
            u64 acc[8];
#pragma unroll
            for (int p = 0; p < 8; ++p) acc[p] = 0ull;

#pragma unroll 2
            for (int jp = 0; jp < 16; ++jp) {
                u64 cpair = scmodp_col[jp * TPB];
#pragma unroll
                for (int sub = 0; sub < 2; ++sub) {
                    const int j = 2 * jp + sub;
                    float cj = sub ? hi32f(cpair) : lo32f(cpair);
                    u64 sp = pack2(cj, 0.0f);
                    const U128* wq = reinterpret_cast<const U128*>(&sWtI[j * 8]);
                    U128 q0 = wq[0], q1 = wq[1], q2 = wq[2], q3 = wq[3];
                    ffma2(sp, vpack[0], q0.u[0]); ffma2(sp, vpack[1], q0.u[1]);
                    ffma2(sp, vpack[2], q1.u[0]); ffma2(sp, vpack[3], q1.u[1]);
                    ffma2(sp, vpack[4], q2.u[0]); ffma2(sp, vpack[5], q2.u[1]);
                    ffma2(sp, vpack[6], q3.u[0]); ffma2(sp, vpack[7], q3.u[1]);
                    // scaled dot -> e^{-s} directly
                    float ex = ex2f(lo32f(sp) + hi32f(sp));
                    float u = u01(tf_bits_pc(K1, hoff + (uint32_t)j));
                    float h = (fmaf(u, ex, u) < 1.0f) ? 1.0f : 0.0f;
                    u64 h2 = dup2(h);
                    ffma2(acc[0], h2, q0.u[0]); ffma2(acc[1], h2, q0.u[1]);
                    ffma2(acc[2], h2, q1.u[0]); ffma2(acc[3], h2, q1.u[1]);
                    ffma2(acc[4], h2, q2.u[0]); ffma2(acc[5], h2, q2.u[1]);
                    ffma2(acc[6], h2, q3.u[0]); ffma2(acc[7], h2, q3.u[1]);
                }
            }

            const TFK K2 = mk_tfk(sk2[s]);
            const uint32_t voff = base_v + K2.k1;
#pragma unroll
            for (int p = 0; p < 8; ++p) {
                u64 sv2 = fadd2(acc[p], sbmod_col[p * TPB]);   // scaled space
                float e0 = ex2f(lo32f(sv2));
                float u0 = u01(tf_bits_pc(K2, voff + (uint32_t)(2 * p)));
                float v0 = (fmaf(u0, e0, u0) < 1.0f) ? 1.0f : 0.0f;
                float e1 = ex2f(hi32f(sv2));
                float u1 = u01(tf_bits_pc(K2, voff + (uint32_t)(2 * p + 1)));
                float v1 = (fmaf(u1, e1, u1) < 1.0f) ? 1.0f : 0.0f;
                vpack[p] = pack2(v0, v1);
            }
        }

        float fe_model = free_energy(vpack, sbmod_col, scmodp_col, sWtI);
        loss = fe_data - fe_model;
    }

    // ---- deterministic block reduction ----
#pragma unroll
    for (int off = 16; off > 0; off >>= 1)
        loss += __shfl_down_sync(0xffffffffu, loss, off);
    if ((t & 31) == 0) swarp[t >> 5] = loss;
    __syncthreads();
    if (t == 0) {
        float tot = 0.0f;
#pragma unroll
        for (int wgi = 0; wgi < TPB / 32; ++wgi) tot += swarp[wgi];
        g_part[blockIdx.x] = tot;
        __threadfence();
        unsigned r = atomicAdd(&g_ticket, 1u);
        sIsLast = (r == gridDim.x - 1) ? 1 : 0;
    }
    __syncthreads();

    // ---- last block: final deterministic reduction ----
    if (sIsLast) {
        __threadfence();
        double accd = 0.0;
        for (int idx = t; idx < (int)gridDim.x; idx += TPB)
            accd += (double)g_part[idx];
        sd[t] = accd;
        __syncthreads();
#pragma unroll
        for (int off = TPB / 2; off > 0; off >>= 1) {
            if (t < off) sd[t] += sd[t + off];
            __syncthreads();
        }
        if (t == 0) {
            out[0] = (float)(sd[0] / (double)batch);
            g_ticket = 0u;   // reset for next graph replay
        }
    }
}

// ---------------------------------------------------------------------------
extern "C" void kernel_launch(void* const* d_in, const int* in_sizes, int n_in,
                              void* d_out, int out_size) {
    const float* v_data = (const float*)d_in[0];
    const float* cond   = (const float*)d_in[1];
    const float* W      = (const float*)d_in[2];
    const float* bias_b = (const float*)d_in[3];
    const float* bias_c = (const float*)d_in[4];
    const float* W1     = (const float*)d_in[5];
    const float* b1     = (const float*)d_in[6];
    const float* W2     = (const float*)d_in[7];
    const float* b2     = (const float*)d_in[8];
    const int*   kp     = (const int*)d_in[9];

    int batch = in_sizes[0] / NV;   // 524288
    int grid = (batch + TPB - 1) / TPB;
    if (grid > MAXBLK) grid = MAXBLK;

    rbm_fused<<<grid, TPB>>>(v_data, cond, W, bias_b, bias_c, W1, b1, W2, b2,
                             kp, (float*)d_out, batch);
}